// round 13
// baseline (speedup 1.0000x reference)
#include <cuda_runtime.h>
#include <cstdint>

#define NCLS 80
#define CAP  512          // per-class candidate cap (mean 315, max ~375 for seed 0)
#define NW   (CAP / 32)   // 16 mask words per row
#define NTOT 25200        // (6400+1600+400)*3
#define TPA  8            // threads per anchor in decode
#define CPA  (NCLS / TPA) // 10 classes per thread
#define NMS_THREADS 1024

// Scratch: per-class candidate lists (key = (~score_bits)<<32 | anchor_idx)
__device__ int d_count[NCLS];                       // zero-initialized at load
__device__ unsigned long long d_list[NCLS * CAP];
__device__ float4 d_boxes[NTOT];                    // decoded boxes for fast gather

__constant__ float c_anch[9][2] = {
    {10.f,13.f},{16.f,30.f},{33.f,23.f},
    {30.f,61.f},{62.f,45.f},{59.f,119.f},
    {116.f,90.f},{156.f,198.f},{373.f,326.f}
};

// fast sigmoid: |err| ~1e-7 relative, ~7 instrs
__device__ __forceinline__ float fsigm(float x) {
    return __fdividef(1.0f, 1.0f + __expf(-x));
}

// Per-level decode with compile-time constants: all div/mod become mul-shift.
template<int HW, int WS, int STRIDEV, int LVL, int GBASE>
__device__ __forceinline__ void decode_level(const float* __restrict__ p,
                                             int tl, int q,
                                             float* __restrict__ out) {
    int a = tl / HW;          // constant divisor -> mul-shift
    int i = tl - a * HW;

    // ---- class softmax pieces: this thread owns classes [q*CPA, q*CPA+CPA) ----
    const float* pc = p + (size_t)(3 + a * 80) * HW + i;
    float v[CPA];
    #pragma unroll
    for (int j = 0; j < CPA; j++)
        v[j] = pc[(size_t)(q * CPA + j) * HW];

    float m = v[0];
    int am = q * CPA;
    #pragma unroll
    for (int j = 1; j < CPA; j++)
        if (v[j] > m) { m = v[j]; am = q * CPA + j; }

    // reduce (max, argmax) across the 8-lane segment; ties -> lower class index
    #pragma unroll
    for (int d = TPA / 2; d > 0; d >>= 1) {
        float om = __shfl_down_sync(0xFFFFFFFFu, m,  d, TPA);
        int   oa = __shfl_down_sync(0xFFFFFFFFu, am, d, TPA);
        if (om > m || (om == m && oa < am)) { m = om; am = oa; }
    }
    m  = __shfl_sync(0xFFFFFFFFu, m,  0, TPA);
    am = __shfl_sync(0xFFFFFFFFu, am, 0, TPA);

    float s = 0.0f;
    #pragma unroll
    for (int j = 0; j < CPA; j++)
        s += __expf(v[j] - m);
    #pragma unroll
    for (int d = TPA / 2; d > 0; d >>= 1)
        s += __shfl_down_sync(0xFFFFFFFFu, s, d, TPA);

    if (q != 0) return;

    // ---- box decode (lane 0 of segment only) ----
    const float* pr = p + (size_t)(243 + a * 4) * HW + i;
    float gx = (float)(i % WS);
    float gy = (float)(i / WS);
    float cx = (fsigm(pr[0])          + gx) * (float)STRIDEV;
    float cy = (fsigm(pr[(size_t)HW]) + gy) * (float)STRIDEV;
    float bw = __expf(pr[(size_t)2 * HW]) * c_anch[LVL * 3 + a][0];
    float bh = __expf(pr[(size_t)3 * HW]) * c_anch[LVL * 3 + a][1];

    float x1 = fminf(fmaxf((cx - bw * 0.5f) / 640.0f, 0.0f), 1.0f);
    float y1 = fminf(fmaxf((cy - bh * 0.5f) / 640.0f, 0.0f), 1.0f);
    float x2 = fminf(fmaxf((cx + bw * 0.5f) / 640.0f, 0.0f), 1.0f);
    float y2 = fminf(fmaxf((cy + bh * 0.5f) / 640.0f, 0.0f), 1.0f);

    float obj   = fsigm(p[(size_t)a * HW + i]);
    float score = __fdividef(obj, s);   // softmax-at-argmax (1/s) * obj

    int g = GBASE + i * 3 + a;
    float* o = out + (size_t)g * 7;
    o[0] = x1; o[1] = y1; o[2] = x2; o[3] = y2;
    o[4] = score;
    o[5] = (float)am;
    o[6] = 0.0f;
    d_boxes[g] = make_float4(x1, y1, x2, y2);

    if (score >= 0.001f) {
        unsigned long long key =
            (((unsigned long long)(0xFFFFFFFFu - __float_as_uint(score))) << 32) |
            (unsigned long long)(unsigned)g;
        int pos = atomicAdd(&d_count[am], 1);
        if (pos < CAP) d_list[(size_t)am * CAP + pos] = key;
    }
}

__global__ void __launch_bounds__(256) decode_kernel(const float* __restrict__ ps,
                                                     const float* __restrict__ pm,
                                                     const float* __restrict__ pl,
                                                     float* __restrict__ out) {
    int t = blockIdx.x * blockDim.x + threadIdx.x;
    int aidx = t >> 3;
    int q    = t & (TPA - 1);
    if (aidx >= NTOT) return;

    if (aidx < 19200)
        decode_level<6400, 80,  8, 0, 0>    (ps, aidx,         q, out);
    else if (aidx < 24000)
        decode_level<1600, 40, 16, 1, 19200>(pm, aidx - 19200, q, out);
    else
        decode_level< 400, 20, 32, 2, 24000>(pl, aidx - 24000, q, out);
}

// IoU suppression test for one (i, j0..j0+31) strip; predicates hoisted.
// Full-tile fast path is unrolled so shift amounts become immediates.
__device__ __forceinline__ unsigned iou_strip(
    const float4* __restrict__ bb, const float* __restrict__ ar2,
    float4 bi, float aI, int j0, int jend)
{
    unsigned bits = 0;
    if (jend - j0 == 32) {
        #pragma unroll
        for (int jj = 0; jj < 32; jj++) {
            int j = j0 + jj;
            float4 bj = bb[j];
            float xx1 = fmaxf(bi.x, bj.x);
            float yy1 = fmaxf(bi.y, bj.y);
            float xx2 = fminf(bi.z, bj.z);
            float yy2 = fminf(bi.w, bj.w);
            float w_ = fmaxf(1e-28f, xx2 - xx1);
            float h_ = fmaxf(1e-28f, yy2 - yy1);
            float inter = w_ * h_;
            float denom = (aI + ar2[j]) - inter;
            if (inter > 0.599f * denom) {            // prefilter (denom<0 -> div<=0)
                if (inter / denom > 0.6f) bits |= (1u << jj);
            }
        }
    } else {
        for (int j = j0; j < jend; j++) {
            float4 bj = bb[j];
            float xx1 = fmaxf(bi.x, bj.x);
            float yy1 = fmaxf(bi.y, bj.y);
            float xx2 = fminf(bi.z, bj.z);
            float yy2 = fminf(bi.w, bj.w);
            float w_ = fmaxf(1e-28f, xx2 - xx1);
            float h_ = fmaxf(1e-28f, yy2 - yy1);
            float inter = w_ * h_;
            float denom = (aI + ar2[j]) - inter;
            if (inter > 0.599f * denom) {
                if (inter / denom > 0.6f) bits |= (1u << (j - j0));
            }
        }
    }
    return bits;
}

// One block (1024 threads) per class.
// 1) hybrid register/shfl bitonic sort over 512 slots
// 2) tile-balanced mask build: 32x32 upper-triangle tiles over 32 warps
// 3) colOr reduction + interesting-rows-only serial scan + parallel keep-write.
__global__ void __launch_bounds__(NMS_THREADS, 1) nms_kernel(float* __restrict__ out) {
    int c    = blockIdx.x;
    int tid  = threadIdx.x;
    int lane = tid & 31;
    int warp = tid >> 5;

    __shared__ unsigned long long keys[CAP];     //  4 KB
    __shared__ float4  bb[CAP];                  //  8 KB
    __shared__ float   ar2[CAP];                 //  2 KB precomputed areas
    __shared__ unsigned maskT[NW * CAP];         // 32 KB transposed suppression matrix
    __shared__ unsigned flagw[NW];               // row-flag bits (row suppresses someone)
    __shared__ unsigned colOr[NW];               // column-OR bits (row is suppressible)
    __shared__ unsigned rem_sh[NW];              // final removed bits
    __shared__ int sn;

    if (tid == 0) {
        int nn = d_count[c];
        sn = (nn > CAP) ? CAP : nn;
        d_count[c] = 0;                          // reset for next replay
    }
    if (tid < NW) flagw[tid] = 0;

    // coalesced conflict-free zero of maskT (2 STS.128 per thread)
    {
        uint4 z = make_uint4(0, 0, 0, 0);
        uint4* mz = (uint4*)maskT;
        #pragma unroll
        for (int k = 0; k < (NW * CAP / 4) / NMS_THREADS; k++)
            mz[tid + k * NMS_THREADS] = z;
    }
    __syncthreads();
    int n = sn;

    // ---- sort: threads 0..511 own one key each ----
    unsigned long long r = 0xFFFFFFFFFFFFFFFFULL;
    if (tid < CAP && tid < n)
        r = d_list[(size_t)c * CAP + tid];

    if (tid < CAP) {
        #pragma unroll
        for (int k = 2; k <= 32; k <<= 1) {
            bool up = ((tid & k) == 0);
            #pragma unroll
            for (int j = k >> 1; j >= 1; j >>= 1) {
                unsigned long long o = __shfl_xor_sync(0xFFFFFFFFu, r, j);
                bool takeMin = (((tid & j) == 0) == up);
                bool less = (o < r);
                r = takeMin ? (less ? o : r) : (less ? r : o);
            }
        }
    }
    #pragma unroll
    for (int k = 64; k <= CAP; k <<= 1) {
        bool up = ((tid & k) == 0);
        for (int j = k >> 1; j >= 32; j >>= 1) {
            if (tid < CAP) keys[tid] = r;
            __syncthreads();
            if (tid < CAP) {
                unsigned long long o = keys[tid ^ j];
                bool takeMin = (((tid & j) == 0) == up);
                bool less = (o < r);
                r = takeMin ? (less ? o : r) : (less ? r : o);
            }
            __syncthreads();
        }
        if (tid < CAP) {
            #pragma unroll
            for (int j = 16; j >= 1; j >>= 1) {
                unsigned long long o = __shfl_xor_sync(0xFFFFFFFFu, r, j);
                bool takeMin = (((tid & j) == 0) == up);
                bool less = (o < r);
                r = takeMin ? (less ? o : r) : (less ? r : o);
            }
        }
    }
    if (tid < CAP) keys[tid] = r;
    __syncthreads();

    // ---- gather boxes + areas in sorted order, with class offset ----
    float off = 2.0f * (float)c;
    if (tid < n) {
        int idx = (int)(keys[tid] & 0xFFFFFFFFULL);
        float4 b = d_boxes[idx];                 // one LDG.128
        float4 bo = make_float4(b.x + off, b.y + off, b.z + off, b.w + off);
        bb[tid]  = bo;
        ar2[tid] = (bo.z - bo.x) * (bo.w - bo.y);
    }
    __syncthreads();

    // ---- tile-balanced mask build (32 warps) ----
    {
        int nb = (n + 31) >> 5;
        int T  = nb * (nb + 1) >> 1;
        for (int t = warp; t < T; t += NMS_THREADS / 32) {
            int rb = 0, tt = t;
            while (tt >= nb - rb) { tt -= nb - rb; rb++; }
            int w = rb + tt;

            int i = (rb << 5) + lane;
            float4 bi = bb[i];
            float aI = ar2[i];

            int j0   = w << 5;
            int jend = min(j0 + 32, n);
            unsigned bits = iou_strip(bb, ar2, bi, aI, j0, jend);

            if (w == rb)                          // diagonal: clear j <= i
                bits &= ~(0xFFFFFFFFu >> (31 - lane));
            if (i >= n) bits = 0;                 // invalid rows

            if (bits) maskT[w * CAP + i] = bits;  // conflict-free STS
            unsigned bal = __ballot_sync(0xFFFFFFFFu, bits != 0);
            if (lane == 0 && bal) atomicOr(&flagw[rb], bal);
        }
    }
    __syncthreads();

    // ---- column-OR reduction: warp w owns mask word w across all rows ----
    if (warp < NW) {
        unsigned v2 = 0;
        #pragma unroll
        for (int k = 0; k < NW; k++)
            v2 |= maskT[warp * CAP + (k << 5) + lane];   // conflict-free
        #pragma unroll
        for (int d = 16; d >= 1; d >>= 1)
            v2 |= __shfl_xor_sync(0xFFFFFFFFu, v2, d);
        if (lane == 0) colOr[warp] = v2;
    }
    __syncthreads();

    // ---- serial scan over INTERESTING rows only (usually a handful) ----
    if (tid == 0) {
        unsigned rem[NW];
        #pragma unroll
        for (int w = 0; w < NW; w++) rem[w] = 0;

        #pragma unroll
        for (int w = 0; w < NW; w++) {
            int base = w << 5;
            if (base < n) {
                unsigned valid = (n - base >= 32) ? 0xFFFFFFFFu
                                                  : ((1u << (n - base)) - 1u);
                unsigned fw = flagw[w];
                unsigned u  = (fw | colOr[w]) & valid;   // interesting rows
                while (u) {
                    int b = __ffs(u) - 1;
                    u &= u - 1;
                    if (!((rem[w] >> b) & 1u) && ((fw >> b) & 1u)) {
                        int i = base + b;                // kept suppressor: apply row
                        #pragma unroll
                        for (int ww = 0; ww < NW; ww++)
                            rem[ww] |= maskT[ww * CAP + i];
                    }
                }
            }
        }
        #pragma unroll
        for (int w = 0; w < NW; w++) rem_sh[w] = rem[w];
    }
    __syncthreads();

    // ---- parallel keep-write ----
    if (tid < n) {
        if (!((rem_sh[tid >> 5] >> (tid & 31)) & 1u))
            out[(size_t)((int)(keys[tid] & 0xFFFFFFFFULL)) * 7 + 6] = 1.0f;
    }
}

extern "C" void kernel_launch(void* const* d_in, const int* in_sizes, int n_in,
                              void* d_out, int out_size) {
    const float* ps = (const float*)d_in[0];
    const float* pm = (const float*)d_in[1];
    const float* pl = (const float*)d_in[2];
    float* out = (float*)d_out;

    decode_kernel<<<(NTOT * TPA + 255) / 256, 256>>>(ps, pm, pl, out);
    nms_kernel<<<NCLS, NMS_THREADS>>>(out);
}

// round 14
// speedup vs baseline: 1.3801x; 1.3801x over previous
#include <cuda_runtime.h>
#include <cstdint>

#define NCLS 80
#define CAP  512          // per-class candidate cap (mean 315, max ~375 for seed 0)
#define NW   (CAP / 32)   // 16 mask words per row
#define NTOT 25200        // (6400+1600+400)*3
#define TPA  8            // threads per anchor in decode
#define CPA  (NCLS / TPA) // 10 classes per thread
#define NMS_THREADS 1024

// Scratch: per-class candidate lists (key = (~score_bits)<<32 | anchor_idx)
__device__ int d_count[NCLS];                       // zero-initialized at load
__device__ unsigned long long d_list[NCLS * CAP];
__device__ float4 d_boxes[NTOT];                    // decoded boxes for fast gather

__constant__ float c_anch[9][2] = {
    {10.f,13.f},{16.f,30.f},{33.f,23.f},
    {30.f,61.f},{62.f,45.f},{59.f,119.f},
    {116.f,90.f},{156.f,198.f},{373.f,326.f}
};

// fast sigmoid: |err| ~1e-7 relative
__device__ __forceinline__ float fsigm(float x) {
    return __fdividef(1.0f, 1.0f + __expf(-x));
}

// Per-level decode with compile-time constants: all div/mod become mul-shift.
template<int HW, int WS, int STRIDEV, int LVL, int GBASE>
__device__ __forceinline__ void decode_level(const float* __restrict__ p,
                                             int tl, int q,
                                             float* __restrict__ out) {
    int a = tl / HW;          // constant divisor -> mul-shift
    int i = tl - a * HW;

    // ---- class softmax pieces: this thread owns classes [q*CPA, q*CPA+CPA) ----
    const float* pc = p + (size_t)(3 + a * 80) * HW + i;
    float v[CPA];
    #pragma unroll
    for (int j = 0; j < CPA; j++)
        v[j] = pc[(size_t)(q * CPA + j) * HW];

    float m = v[0];
    int am = q * CPA;
    #pragma unroll
    for (int j = 1; j < CPA; j++)
        if (v[j] > m) { m = v[j]; am = q * CPA + j; }

    // reduce (max, argmax) across the 8-lane segment; ties -> lower class index
    #pragma unroll
    for (int d = TPA / 2; d > 0; d >>= 1) {
        float om = __shfl_down_sync(0xFFFFFFFFu, m,  d, TPA);
        int   oa = __shfl_down_sync(0xFFFFFFFFu, am, d, TPA);
        if (om > m || (om == m && oa < am)) { m = om; am = oa; }
    }
    m  = __shfl_sync(0xFFFFFFFFu, m,  0, TPA);
    am = __shfl_sync(0xFFFFFFFFu, am, 0, TPA);

    float s = 0.0f;
    #pragma unroll
    for (int j = 0; j < CPA; j++)
        s += __expf(v[j] - m);
    #pragma unroll
    for (int d = TPA / 2; d > 0; d >>= 1)
        s += __shfl_down_sync(0xFFFFFFFFu, s, d, TPA);

    if (q != 0) return;

    // ---- box decode (lane 0 of segment only) ----
    const float* pr = p + (size_t)(243 + a * 4) * HW + i;
    float gx = (float)(i % WS);
    float gy = (float)(i / WS);
    float cx = (fsigm(pr[0])          + gx) * (float)STRIDEV;
    float cy = (fsigm(pr[(size_t)HW]) + gy) * (float)STRIDEV;
    float bw = __expf(pr[(size_t)2 * HW]) * c_anch[LVL * 3 + a][0];
    float bh = __expf(pr[(size_t)3 * HW]) * c_anch[LVL * 3 + a][1];

    float x1 = fminf(fmaxf((cx - bw * 0.5f) / 640.0f, 0.0f), 1.0f);
    float y1 = fminf(fmaxf((cy - bh * 0.5f) / 640.0f, 0.0f), 1.0f);
    float x2 = fminf(fmaxf((cx + bw * 0.5f) / 640.0f, 0.0f), 1.0f);
    float y2 = fminf(fmaxf((cy + bh * 0.5f) / 640.0f, 0.0f), 1.0f);

    float obj   = fsigm(p[(size_t)a * HW + i]);
    float score = __fdividef(obj, s);   // softmax-at-argmax (1/s) * obj

    int g = GBASE + i * 3 + a;
    float* o = out + (size_t)g * 7;
    o[0] = x1; o[1] = y1; o[2] = x2; o[3] = y2;
    o[4] = score;
    o[5] = (float)am;
    o[6] = 0.0f;
    d_boxes[g] = make_float4(x1, y1, x2, y2);

    if (score >= 0.001f) {
        unsigned long long key =
            (((unsigned long long)(0xFFFFFFFFu - __float_as_uint(score))) << 32) |
            (unsigned long long)(unsigned)g;
        int pos = atomicAdd(&d_count[am], 1);
        if (pos < CAP) d_list[(size_t)am * CAP + pos] = key;
    }
}

__global__ void __launch_bounds__(256) decode_kernel(const float* __restrict__ ps,
                                                     const float* __restrict__ pm,
                                                     const float* __restrict__ pl,
                                                     float* __restrict__ out) {
    int t = blockIdx.x * blockDim.x + threadIdx.x;
    int aidx = t >> 3;
    int q    = t & (TPA - 1);
    if (aidx >= NTOT) return;

    if (aidx < 19200)
        decode_level<6400, 80,  8, 0, 0>    (ps, aidx,         q, out);
    else if (aidx < 24000)
        decode_level<1600, 40, 16, 1, 19200>(pm, aidx - 19200, q, out);
    else
        decode_level< 400, 20, 32, 2, 24000>(pl, aidx - 24000, q, out);
}

// IoU suppression test for one (i, j0..j0+31) strip; predicates hoisted.
// Full-tile fast path is unrolled so shift amounts become immediates.
__device__ __forceinline__ unsigned iou_strip(
    const float4* __restrict__ bb, const float* __restrict__ ar2,
    float4 bi, float aI, int j0, int jend)
{
    unsigned bits = 0;
    if (jend - j0 == 32) {
        #pragma unroll
        for (int jj = 0; jj < 32; jj++) {
            int j = j0 + jj;
            float4 bj = bb[j];
            float xx1 = fmaxf(bi.x, bj.x);
            float yy1 = fmaxf(bi.y, bj.y);
            float xx2 = fminf(bi.z, bj.z);
            float yy2 = fminf(bi.w, bj.w);
            float w_ = fmaxf(1e-28f, xx2 - xx1);
            float h_ = fmaxf(1e-28f, yy2 - yy1);
            float inter = w_ * h_;
            float denom = (aI + ar2[j]) - inter;
            if (inter > 0.599f * denom) {            // prefilter (denom<0 -> div<=0)
                if (inter / denom > 0.6f) bits |= (1u << jj);
            }
        }
    } else {
        for (int j = j0; j < jend; j++) {
            float4 bj = bb[j];
            float xx1 = fmaxf(bi.x, bj.x);
            float yy1 = fmaxf(bi.y, bj.y);
            float xx2 = fminf(bi.z, bj.z);
            float yy2 = fminf(bi.w, bj.w);
            float w_ = fmaxf(1e-28f, xx2 - xx1);
            float h_ = fmaxf(1e-28f, yy2 - yy1);
            float inter = w_ * h_;
            float denom = (aI + ar2[j]) - inter;
            if (inter > 0.599f * denom) {
                if (inter / denom > 0.6f) bits |= (1u << (j - j0));
            }
        }
    }
    return bits;
}

// One block (1024 threads) per class.
// 1) hybrid register/shfl bitonic sort over 512 slots
// 2) tile-balanced mask build: 32x32 upper-triangle tiles over 32 warps,
//    closed-form triangular tile mapping (no per-tile while-walk)
// 3) colOr reduction + interesting-rows-only serial scan + parallel keep-write.
__global__ void __launch_bounds__(NMS_THREADS, 1) nms_kernel(float* __restrict__ out) {
    int c    = blockIdx.x;
    int tid  = threadIdx.x;
    int lane = tid & 31;
    int warp = tid >> 5;

    __shared__ unsigned long long keys[CAP];     //  4 KB
    __shared__ float4  bb[CAP];                  //  8 KB
    __shared__ float   ar2[CAP];                 //  2 KB precomputed areas
    __shared__ unsigned maskT[NW * CAP];         // 32 KB transposed suppression matrix
    __shared__ unsigned flagw[NW];               // row-flag bits (row suppresses someone)
    __shared__ unsigned colOr[NW];               // column-OR bits (row is suppressible)
    __shared__ unsigned rem_sh[NW];              // final removed bits
    __shared__ int sn;

    if (tid == 0) {
        int nn = d_count[c];
        sn = (nn > CAP) ? CAP : nn;
        d_count[c] = 0;                          // reset for next replay
    }
    if (tid < NW) flagw[tid] = 0;

    // coalesced conflict-free zero of maskT (2 STS.128 per thread)
    {
        uint4 z = make_uint4(0, 0, 0, 0);
        uint4* mz = (uint4*)maskT;
        #pragma unroll
        for (int k = 0; k < (NW * CAP / 4) / NMS_THREADS; k++)
            mz[tid + k * NMS_THREADS] = z;
    }
    __syncthreads();
    int n = sn;

    // ---- sort: threads 0..511 own one key each ----
    unsigned long long r = 0xFFFFFFFFFFFFFFFFULL;
    if (tid < CAP && tid < n)
        r = d_list[(size_t)c * CAP + tid];

    if (tid < CAP) {
        #pragma unroll
        for (int k = 2; k <= 32; k <<= 1) {
            bool up = ((tid & k) == 0);
            #pragma unroll
            for (int j = k >> 1; j >= 1; j >>= 1) {
                unsigned long long o = __shfl_xor_sync(0xFFFFFFFFu, r, j);
                bool takeMin = (((tid & j) == 0) == up);
                bool less = (o < r);
                r = takeMin ? (less ? o : r) : (less ? r : o);
            }
        }
    }
    #pragma unroll
    for (int k = 64; k <= CAP; k <<= 1) {
        bool up = ((tid & k) == 0);
        for (int j = k >> 1; j >= 32; j >>= 1) {
            if (tid < CAP) keys[tid] = r;
            __syncthreads();
            if (tid < CAP) {
                unsigned long long o = keys[tid ^ j];
                bool takeMin = (((tid & j) == 0) == up);
                bool less = (o < r);
                r = takeMin ? (less ? o : r) : (less ? r : o);
            }
            __syncthreads();
        }
        if (tid < CAP) {
            #pragma unroll
            for (int j = 16; j >= 1; j >>= 1) {
                unsigned long long o = __shfl_xor_sync(0xFFFFFFFFu, r, j);
                bool takeMin = (((tid & j) == 0) == up);
                bool less = (o < r);
                r = takeMin ? (less ? o : r) : (less ? r : o);
            }
        }
    }
    if (tid < CAP) keys[tid] = r;
    __syncthreads();

    // ---- gather boxes + areas in sorted order, with class offset ----
    float off = 2.0f * (float)c;
    if (tid < n) {
        int idx = (int)(keys[tid] & 0xFFFFFFFFULL);
        float4 b = d_boxes[idx];                 // one LDG.128
        float4 bo = make_float4(b.x + off, b.y + off, b.z + off, b.w + off);
        bb[tid]  = bo;
        ar2[tid] = (bo.z - bo.x) * (bo.w - bo.y);
    }
    __syncthreads();

    // ---- tile-balanced mask build (32 warps) ----
    {
        int nb = (n + 31) >> 5;
        int T  = nb * (nb + 1) >> 1;
        for (int t = warp; t < T; t += NMS_THREADS / 32) {
            // closed-form triangular inversion: find rb s.t.
            // rb*nb - rb(rb-1)/2 <= t ; u = T-1-t maps to reversed triangle
            int u  = T - 1 - t;
            int rr = (int)((sqrtf(8.0f * (float)u + 1.0f) - 1.0f) * 0.5f);
            // guard float rounding (at most one step either way)
            if ((rr + 1) * (rr + 2) / 2 <= u) rr++;
            if (rr * (rr + 1) / 2 > u)        rr--;
            int rb = nb - 1 - rr;
            int w  = nb - 1 - (u - rr * (rr + 1) / 2);

            int i = (rb << 5) + lane;
            float4 bi = bb[i];
            float aI = ar2[i];

            int j0   = w << 5;
            int jend = min(j0 + 32, n);
            unsigned bits = iou_strip(bb, ar2, bi, aI, j0, jend);

            if (w == rb)                          // diagonal: clear j <= i
                bits &= ~(0xFFFFFFFFu >> (31 - lane));
            if (i >= n) bits = 0;                 // invalid rows

            if (bits) maskT[w * CAP + i] = bits;  // conflict-free STS
            unsigned bal = __ballot_sync(0xFFFFFFFFu, bits != 0);
            if (lane == 0 && bal) atomicOr(&flagw[rb], bal);
        }
    }
    __syncthreads();

    // ---- column-OR reduction: warp w owns mask word w across all rows ----
    if (warp < NW) {
        unsigned v2 = 0;
        #pragma unroll
        for (int k = 0; k < NW; k++)
            v2 |= maskT[warp * CAP + (k << 5) + lane];   // conflict-free
        #pragma unroll
        for (int d = 16; d >= 1; d >>= 1)
            v2 |= __shfl_xor_sync(0xFFFFFFFFu, v2, d);
        if (lane == 0) colOr[warp] = v2;
    }
    __syncthreads();

    // ---- serial scan over INTERESTING rows only (usually a handful) ----
    if (tid == 0) {
        unsigned rem[NW];
        #pragma unroll
        for (int w = 0; w < NW; w++) rem[w] = 0;

        #pragma unroll
        for (int w = 0; w < NW; w++) {
            int base = w << 5;
            if (base < n) {
                unsigned valid = (n - base >= 32) ? 0xFFFFFFFFu
                                                  : ((1u << (n - base)) - 1u);
                unsigned fw = flagw[w];
                unsigned u  = (fw | colOr[w]) & valid;   // interesting rows
                while (u) {
                    int b = __ffs(u) - 1;
                    u &= u - 1;
                    if (!((rem[w] >> b) & 1u) && ((fw >> b) & 1u)) {
                        int i = base + b;                // kept suppressor: apply row
                        #pragma unroll
                        for (int ww = 0; ww < NW; ww++)
                            rem[ww] |= maskT[ww * CAP + i];
                    }
                }
            }
        }
        #pragma unroll
        for (int w = 0; w < NW; w++) rem_sh[w] = rem[w];
    }
    __syncthreads();

    // ---- parallel keep-write ----
    if (tid < n) {
        if (!((rem_sh[tid >> 5] >> (tid & 31)) & 1u))
            out[(size_t)((int)(keys[tid] & 0xFFFFFFFFULL)) * 7 + 6] = 1.0f;
    }
}

extern "C" void kernel_launch(void* const* d_in, const int* in_sizes, int n_in,
                              void* d_out, int out_size) {
    const float* ps = (const float*)d_in[0];
    const float* pm = (const float*)d_in[1];
    const float* pl = (const float*)d_in[2];
    float* out = (float*)d_out;

    decode_kernel<<<(NTOT * TPA + 255) / 256, 256>>>(ps, pm, pl, out);
    nms_kernel<<<NCLS, NMS_THREADS>>>(out);
}

// round 15
// speedup vs baseline: 1.4876x; 1.0779x over previous
#include <cuda_runtime.h>
#include <cstdint>

#define NCLS 80
#define CAP  512          // per-class candidate cap (mean 315, max ~375 for seed 0)
#define NW   (CAP / 32)   // 16 mask words per row
#define NTOT 25200        // (6400+1600+400)*3
#define TPA  4            // threads per anchor in decode (8 anchors/warp -> full sectors)
#define CPA  (NCLS / TPA) // 20 classes per thread
#define NMS_THREADS 1024

// Scratch: per-class candidate lists (key = (~score_bits)<<32 | anchor_idx)
__device__ int d_count[NCLS];                       // zero-initialized at load
__device__ unsigned long long d_list[NCLS * CAP];
__device__ float4 d_boxes[NTOT];                    // decoded boxes for fast gather

__constant__ float c_anch[9][2] = {
    {10.f,13.f},{16.f,30.f},{33.f,23.f},
    {30.f,61.f},{62.f,45.f},{59.f,119.f},
    {116.f,90.f},{156.f,198.f},{373.f,326.f}
};

// fast sigmoid: |err| ~1e-7 relative
__device__ __forceinline__ float fsigm(float x) {
    return __fdividef(1.0f, 1.0f + __expf(-x));
}

// Per-level decode with compile-time constants: all div/mod become mul-shift.
template<int HW, int WS, int STRIDEV, int LVL, int GBASE>
__device__ __forceinline__ void decode_level(const float* __restrict__ p,
                                             int tl, int q,
                                             float* __restrict__ out) {
    int a = tl / HW;          // constant divisor -> mul-shift
    int i = tl - a * HW;

    // ---- class softmax pieces: this thread owns classes [q*CPA, q*CPA+CPA) ----
    const float* pc = p + (size_t)(3 + a * 80) * HW + i;
    float v[CPA];
    #pragma unroll
    for (int j = 0; j < CPA; j++)
        v[j] = pc[(size_t)(q * CPA + j) * HW];

    float m = v[0];
    int am = q * CPA;
    #pragma unroll
    for (int j = 1; j < CPA; j++)
        if (v[j] > m) { m = v[j]; am = q * CPA + j; }

    // reduce (max, argmax) across the 4-lane segment; ties -> lower class index
    #pragma unroll
    for (int d = TPA / 2; d > 0; d >>= 1) {
        float om = __shfl_down_sync(0xFFFFFFFFu, m,  d, TPA);
        int   oa = __shfl_down_sync(0xFFFFFFFFu, am, d, TPA);
        if (om > m || (om == m && oa < am)) { m = om; am = oa; }
    }
    m  = __shfl_sync(0xFFFFFFFFu, m,  0, TPA);
    am = __shfl_sync(0xFFFFFFFFu, am, 0, TPA);

    float s = 0.0f;
    #pragma unroll
    for (int j = 0; j < CPA; j++)
        s += __expf(v[j] - m);
    #pragma unroll
    for (int d = TPA / 2; d > 0; d >>= 1)
        s += __shfl_down_sync(0xFFFFFFFFu, s, d, TPA);

    if (q != 0) return;

    // ---- box decode (lane 0 of segment only; 8 active lanes/warp, consecutive i) ----
    const float* pr = p + (size_t)(243 + a * 4) * HW + i;
    float gx = (float)(i % WS);
    float gy = (float)(i / WS);
    float cx = (fsigm(pr[0])          + gx) * (float)STRIDEV;
    float cy = (fsigm(pr[(size_t)HW]) + gy) * (float)STRIDEV;
    float bw = __expf(pr[(size_t)2 * HW]) * c_anch[LVL * 3 + a][0];
    float bh = __expf(pr[(size_t)3 * HW]) * c_anch[LVL * 3 + a][1];

    float x1 = fminf(fmaxf((cx - bw * 0.5f) / 640.0f, 0.0f), 1.0f);
    float y1 = fminf(fmaxf((cy - bh * 0.5f) / 640.0f, 0.0f), 1.0f);
    float x2 = fminf(fmaxf((cx + bw * 0.5f) / 640.0f, 0.0f), 1.0f);
    float y2 = fminf(fmaxf((cy + bh * 0.5f) / 640.0f, 0.0f), 1.0f);

    float obj   = fsigm(p[(size_t)a * HW + i]);
    float score = __fdividef(obj, s);   // softmax-at-argmax (1/s) * obj

    int g = GBASE + i * 3 + a;
    float* o = out + (size_t)g * 7;
    o[0] = x1; o[1] = y1; o[2] = x2; o[3] = y2;
    o[4] = score;
    o[5] = (float)am;
    o[6] = 0.0f;
    d_boxes[g] = make_float4(x1, y1, x2, y2);

    if (score >= 0.001f) {
        unsigned long long key =
            (((unsigned long long)(0xFFFFFFFFu - __float_as_uint(score))) << 32) |
            (unsigned long long)(unsigned)g;
        int pos = atomicAdd(&d_count[am], 1);
        if (pos < CAP) d_list[(size_t)am * CAP + pos] = key;
    }
}

__global__ void __launch_bounds__(256) decode_kernel(const float* __restrict__ ps,
                                                     const float* __restrict__ pm,
                                                     const float* __restrict__ pl,
                                                     float* __restrict__ out) {
    int t = blockIdx.x * blockDim.x + threadIdx.x;
    int aidx = t >> 2;
    int q    = t & (TPA - 1);
    if (aidx >= NTOT) return;

    if (aidx < 19200)
        decode_level<6400, 80,  8, 0, 0>    (ps, aidx,         q, out);
    else if (aidx < 24000)
        decode_level<1600, 40, 16, 1, 19200>(pm, aidx - 19200, q, out);
    else
        decode_level< 400, 20, 32, 2, 24000>(pl, aidx - 24000, q, out);
}

// IoU suppression test for one (i, j0..j0+31) strip; predicates hoisted.
// Full-tile fast path is unrolled so shift amounts become immediates.
__device__ __forceinline__ unsigned iou_strip(
    const float4* __restrict__ bb, const float* __restrict__ ar2,
    float4 bi, float aI, int j0, int jend)
{
    unsigned bits = 0;
    if (jend - j0 == 32) {
        #pragma unroll
        for (int jj = 0; jj < 32; jj++) {
            int j = j0 + jj;
            float4 bj = bb[j];
            float xx1 = fmaxf(bi.x, bj.x);
            float yy1 = fmaxf(bi.y, bj.y);
            float xx2 = fminf(bi.z, bj.z);
            float yy2 = fminf(bi.w, bj.w);
            float w_ = fmaxf(1e-28f, xx2 - xx1);
            float h_ = fmaxf(1e-28f, yy2 - yy1);
            float inter = w_ * h_;
            float denom = (aI + ar2[j]) - inter;
            if (inter > 0.599f * denom) {            // prefilter (denom<0 -> div<=0)
                if (inter / denom > 0.6f) bits |= (1u << jj);
            }
        }
    } else {
        for (int j = j0; j < jend; j++) {
            float4 bj = bb[j];
            float xx1 = fmaxf(bi.x, bj.x);
            float yy1 = fmaxf(bi.y, bj.y);
            float xx2 = fminf(bi.z, bj.z);
            float yy2 = fminf(bi.w, bj.w);
            float w_ = fmaxf(1e-28f, xx2 - xx1);
            float h_ = fmaxf(1e-28f, yy2 - yy1);
            float inter = w_ * h_;
            float denom = (aI + ar2[j]) - inter;
            if (inter > 0.599f * denom) {
                if (inter / denom > 0.6f) bits |= (1u << (j - j0));
            }
        }
    }
    return bits;
}

// One block (1024 threads) per class.
// 1) hybrid register/shfl bitonic sort over 512 slots
// 2) tile-balanced mask build: 32x32 upper-triangle tiles over 32 warps,
//    closed-form triangular tile mapping
// 3) colOr reduction + interesting-rows-only serial scan + parallel keep-write.
__global__ void __launch_bounds__(NMS_THREADS, 1) nms_kernel(float* __restrict__ out) {
    int c    = blockIdx.x;
    int tid  = threadIdx.x;
    int lane = tid & 31;
    int warp = tid >> 5;

    __shared__ unsigned long long keys[CAP];     //  4 KB
    __shared__ float4  bb[CAP];                  //  8 KB
    __shared__ float   ar2[CAP];                 //  2 KB precomputed areas
    __shared__ unsigned maskT[NW * CAP];         // 32 KB transposed suppression matrix
    __shared__ unsigned flagw[NW];               // row-flag bits (row suppresses someone)
    __shared__ unsigned colOr[NW];               // column-OR bits (row is suppressible)
    __shared__ unsigned rem_sh[NW];              // final removed bits
    __shared__ int sn;

    if (tid == 0) {
        int nn = d_count[c];
        sn = (nn > CAP) ? CAP : nn;
        d_count[c] = 0;                          // reset for next replay
    }
    if (tid < NW) flagw[tid] = 0;

    // coalesced conflict-free zero of maskT (2 STS.128 per thread)
    {
        uint4 z = make_uint4(0, 0, 0, 0);
        uint4* mz = (uint4*)maskT;
        #pragma unroll
        for (int k = 0; k < (NW * CAP / 4) / NMS_THREADS; k++)
            mz[tid + k * NMS_THREADS] = z;
    }
    __syncthreads();
    int n = sn;

    // ---- sort: threads 0..511 own one key each ----
    unsigned long long r = 0xFFFFFFFFFFFFFFFFULL;
    if (tid < CAP && tid < n)
        r = d_list[(size_t)c * CAP + tid];

    if (tid < CAP) {
        #pragma unroll
        for (int k = 2; k <= 32; k <<= 1) {
            bool up = ((tid & k) == 0);
            #pragma unroll
            for (int j = k >> 1; j >= 1; j >>= 1) {
                unsigned long long o = __shfl_xor_sync(0xFFFFFFFFu, r, j);
                bool takeMin = (((tid & j) == 0) == up);
                bool less = (o < r);
                r = takeMin ? (less ? o : r) : (less ? r : o);
            }
        }
    }
    #pragma unroll
    for (int k = 64; k <= CAP; k <<= 1) {
        bool up = ((tid & k) == 0);
        for (int j = k >> 1; j >= 32; j >>= 1) {
            if (tid < CAP) keys[tid] = r;
            __syncthreads();
            if (tid < CAP) {
                unsigned long long o = keys[tid ^ j];
                bool takeMin = (((tid & j) == 0) == up);
                bool less = (o < r);
                r = takeMin ? (less ? o : r) : (less ? r : o);
            }
            __syncthreads();
        }
        if (tid < CAP) {
            #pragma unroll
            for (int j = 16; j >= 1; j >>= 1) {
                unsigned long long o = __shfl_xor_sync(0xFFFFFFFFu, r, j);
                bool takeMin = (((tid & j) == 0) == up);
                bool less = (o < r);
                r = takeMin ? (less ? o : r) : (less ? r : o);
            }
        }
    }
    if (tid < CAP) keys[tid] = r;
    __syncthreads();

    // ---- gather boxes + areas in sorted order, with class offset ----
    float off = 2.0f * (float)c;
    if (tid < n) {
        int idx = (int)(keys[tid] & 0xFFFFFFFFULL);
        float4 b = d_boxes[idx];                 // one LDG.128
        float4 bo = make_float4(b.x + off, b.y + off, b.z + off, b.w + off);
        bb[tid]  = bo;
        ar2[tid] = (bo.z - bo.x) * (bo.w - bo.y);
    }
    __syncthreads();

    // ---- tile-balanced mask build (32 warps) ----
    {
        int nb = (n + 31) >> 5;
        int T  = nb * (nb + 1) >> 1;
        for (int t = warp; t < T; t += NMS_THREADS / 32) {
            // closed-form triangular inversion via reversed index
            int u  = T - 1 - t;
            int rr = (int)((sqrtf(8.0f * (float)u + 1.0f) - 1.0f) * 0.5f);
            if ((rr + 1) * (rr + 2) / 2 <= u) rr++;
            if (rr * (rr + 1) / 2 > u)        rr--;
            int rb = nb - 1 - rr;
            int w  = nb - 1 - (u - rr * (rr + 1) / 2);

            int i = (rb << 5) + lane;
            float4 bi = bb[i];
            float aI = ar2[i];

            int j0   = w << 5;
            int jend = min(j0 + 32, n);
            unsigned bits = iou_strip(bb, ar2, bi, aI, j0, jend);

            if (w == rb)                          // diagonal: clear j <= i
                bits &= ~(0xFFFFFFFFu >> (31 - lane));
            if (i >= n) bits = 0;                 // invalid rows

            if (bits) maskT[w * CAP + i] = bits;  // conflict-free STS
            unsigned bal = __ballot_sync(0xFFFFFFFFu, bits != 0);
            if (lane == 0 && bal) atomicOr(&flagw[rb], bal);
        }
    }
    __syncthreads();

    // ---- column-OR reduction: warp w owns mask word w across all rows ----
    if (warp < NW) {
        unsigned v2 = 0;
        #pragma unroll
        for (int k = 0; k < NW; k++)
            v2 |= maskT[warp * CAP + (k << 5) + lane];   // conflict-free
        #pragma unroll
        for (int d = 16; d >= 1; d >>= 1)
            v2 |= __shfl_xor_sync(0xFFFFFFFFu, v2, d);
        if (lane == 0) colOr[warp] = v2;
    }
    __syncthreads();

    // ---- serial scan over INTERESTING rows only (usually a handful) ----
    if (tid == 0) {
        unsigned rem[NW];
        #pragma unroll
        for (int w = 0; w < NW; w++) rem[w] = 0;

        #pragma unroll
        for (int w = 0; w < NW; w++) {
            int base = w << 5;
            if (base < n) {
                unsigned valid = (n - base >= 32) ? 0xFFFFFFFFu
                                                  : ((1u << (n - base)) - 1u);
                unsigned fw = flagw[w];
                unsigned u  = (fw | colOr[w]) & valid;   // interesting rows
                while (u) {
                    int b = __ffs(u) - 1;
                    u &= u - 1;
                    if (!((rem[w] >> b) & 1u) && ((fw >> b) & 1u)) {
                        int i = base + b;                // kept suppressor: apply row
                        #pragma unroll
                        for (int ww = 0; ww < NW; ww++)
                            rem[ww] |= maskT[ww * CAP + i];
                    }
                }
            }
        }
        #pragma unroll
        for (int w = 0; w < NW; w++) rem_sh[w] = rem[w];
    }
    __syncthreads();

    // ---- parallel keep-write ----
    if (tid < n) {
        if (!((rem_sh[tid >> 5] >> (tid & 31)) & 1u))
            out[(size_t)((int)(keys[tid] & 0xFFFFFFFFULL)) * 7 + 6] = 1.0f;
    }
}

extern "C" void kernel_launch(void* const* d_in, const int* in_sizes, int n_in,
                              void* d_out, int out_size) {
    const float* ps = (const float*)d_in[0];
    const float* pm = (const float*)d_in[1];
    const float* pl = (const float*)d_in[2];
    float* out = (float*)d_out;

    decode_kernel<<<(NTOT * TPA + 255) / 256, 256>>>(ps, pm, pl, out);
    nms_kernel<<<NCLS, NMS_THREADS>>>(out);
}